// round 16
// baseline (speedup 1.0000x reference)
#include <cuda_runtime.h>
#include <cuda_fp16.h>
#include <cuda.h>
#include <cstdint>

// Problem constants
#define B_  64
#define L_  1024
#define H_  128

// ---------------------------------------------------------------------------
// Scratch (allocation-free rule: __device__ globals)
// fp16 1-term scheme: ah = fp16(body*w3); ph = fp16(pun); s_cross ≈ ah·ph
// (measured rel_err 1.75e-4, deterministic inputs)
// A-side (ah, sbody) computed INSIDE the gemm kernel (tile-local, coalesced);
// prep only produces Ph + spun. PDL overlaps gemm's A-convert with prep.
// ---------------------------------------------------------------------------
__device__ __align__(16) __half g_Ph[(size_t)B_*L_*H_];
__device__ float g_spun [B_*L_];

// ---------------------------------------------------------------------------
// Helpers (base-arch only: NO tcgen05 — ptxas target is sm_103, not sm_103a.
// cp.async.bulk.tensor and griddepcontrol ARE base sm_90+.)
// ---------------------------------------------------------------------------
__device__ __forceinline__ uint32_t smem_u32(const void* p) {
    uint32_t a;
    asm("{ .reg .u64 t; cvta.to.shared.u64 t, %1; cvt.u32.u64 %0, t; }" : "=r"(a) : "l"(p));
    return a;
}

__device__ __forceinline__ void ldsm_x4(uint32_t* r, uint32_t addr) {
    asm volatile("ldmatrix.sync.aligned.m8n8.x4.shared.b16 {%0,%1,%2,%3}, [%4];"
        : "=r"(r[0]), "=r"(r[1]), "=r"(r[2]), "=r"(r[3]) : "r"(addr));
}

// D += A * B  (m16n8k16, fp16 in, f32 accum)
__device__ __forceinline__ void mma_f16(float* d, const uint32_t* a, const uint32_t* b) {
    asm volatile(
        "mma.sync.aligned.m16n8k16.row.col.f32.f16.f16.f32 "
        "{%0,%1,%2,%3}, {%4,%5,%6,%7}, {%8,%9}, {%0,%1,%2,%3};"
        : "+f"(d[0]), "+f"(d[1]), "+f"(d[2]), "+f"(d[3])
        : "r"(a[0]), "r"(a[1]), "r"(a[2]), "r"(a[3]), "r"(b[0]), "r"(b[1]));
}

__device__ __forceinline__ void cp_async16(uint32_t dst, const void* src) {
    asm volatile("cp.async.cg.shared.global [%0], [%1], 16;" :: "r"(dst), "l"(src));
}
#define CP_COMMIT() asm volatile("cp.async.commit_group;" ::: "memory")
#define CP_WAIT(n)  asm volatile("cp.async.wait_group %0;" :: "n"(n) : "memory")
#define BULK_WAIT0() asm volatile("cp.async.bulk.wait_group 0;" ::: "memory")
#define GRIDDEP_WAIT()   asm volatile("griddepcontrol.wait;" ::: "memory")
#define GRIDDEP_LAUNCH() asm volatile("griddepcontrol.launch_dependents;" ::: "memory")

// SW128 swizzle for 128B-pitch rows (epilogue staging / TMA)
__device__ __forceinline__ uint32_t sw128(uint32_t byte_off) {
    return byte_off ^ ((byte_off >> 3) & 0x70u);
}

__device__ __forceinline__ uint32_t pack_h2(float x, float y) {
    __half2 v(__float2half(x), __float2half(y));
    return *reinterpret_cast<uint32_t*>(&v);
}

// ---------------------------------------------------------------------------
// Kernel 1: preprocess (P-side only) — ph = fp16(pun); spun = dot(pun, w2).
// Ends with griddepcontrol.launch_dependents so gemm can launch early (PDL).
// ---------------------------------------------------------------------------
__global__ void __launch_bounds__(256) prep_kernel(const float* __restrict__ pun,
                                                   const float* __restrict__ w_u) {
    const int warp = threadIdx.x >> 5, lane = threadIdx.x & 31;
    const int r = blockIdx.x * 8 + warp;
    const int d4 = lane * 4;

    const float4 w2 = *reinterpret_cast<const float4*>(w_u + H_ + d4);
    const size_t idx = (size_t)r * H_ + d4;
    const float4 pv = *reinterpret_cast<const float4*>(pun + idx);

    *reinterpret_cast<uint2*>(g_Ph + idx) =
        make_uint2(pack_h2(pv.x, pv.y), pack_h2(pv.z, pv.w));

    float sp = pv.x * w2.x + pv.y * w2.y + pv.z * w2.z + pv.w * w2.w;
    #pragma unroll
    for (int o = 16; o > 0; o >>= 1)
        sp += __shfl_down_sync(0xFFFFFFFFu, sp, o);
    if (lane == 0) g_spun[r] = sp;

    GRIDDEP_LAUNCH();
}

// ---------------------------------------------------------------------------
// Kernel 2: occupancy-4 fused-j batched GEMM with coalesced fused A-convert,
// launched via PDL: the A-convert (body/w_u only) runs CONCURRENTLY with
// prep_kernel; griddepcontrol.wait gates only the g_Ph/g_spun consumption.
//   CTA = (64-row i-block, batch), 128 threads, 2x2 warps, warp tile 32x32.
//   A FRAGMENTS HOISTED IN REGISTERS for all 16 j-tiles.
//   P double-buffered (16 KB); epilogue stages both 32x64 regions into the
//   dead P buffer, one TMA group per j.
// Slab format (A and P): rows x 256B (128 fp16); 16B chunk swizzle
//   phys = row*256 + ((ch ^ (row&7))<<4)
// ---------------------------------------------------------------------------
static constexpr int OFF_SB = 0;        // 64 f32 sbody slice (computed in-CTA)
static constexpr int OFF_SP = 512;      // 1024 f32 spun (full row)
static constexpr int OFF_A  = 5120;     // 16 KB A slab (64 rows)
static constexpr int OFF_P0 = 21504;    // 16 KB P slab 0 (64 j-cols)
static constexpr int OFF_P1 = 37888;    // 16 KB P slab 1
static constexpr int SMEM_TOTAL = 54272;    // -> occupancy 4 (regs <= 128)

__device__ __forceinline__ void load_slab64(uint32_t dst, const __half* __restrict__ g,
                                            int row0, int tid) {
    #pragma unroll
    for (int l = 0; l < 8; l++) {
        const int cidx = tid + l * 128;     // 0..1023 16B chunks
        const int row  = cidx >> 4;         // 0..63
        const int ch   = cidx & 15;
        const uint32_t off = (uint32_t)(row * 256 + ((ch ^ (row & 7)) << 4));
        cp_async16(dst + off, g + (size_t)(row0 + row) * H_ + ch * 8);
    }
}

__global__ void __launch_bounds__(128, 4)
gemm_kernel(float* __restrict__ out, const float* __restrict__ body,
            const float* __restrict__ w_u, const __grid_constant__ CUtensorMap tmap) {
    extern __shared__ char smem[];
    const uint32_t sbase = smem_u32(smem);
    const int tid  = threadIdx.x;
    const int lane = tid & 31;
    const int warp = tid >> 5;
    const int wm = warp & 1;            // 2 warps over M (32 rows each)
    const int wn = warp >> 1;           // 2 warps over N (32 cols each)
    const int m_base = wm * 32, n_base = wn * 32;

    const int i0 = blockIdx.x * 64;     // 16 i-blocks of 64 rows
    const int b  = blockIdx.y;
    const size_t base = (size_t)b * L_ * H_;

    // --- fused A-conversion + sbody (coalesced) — INDEPENDENT of prep;
    //     runs while prep_kernel is still executing (PDL overlap) ---
    {
        const int ch      = tid & 15;        // loop-invariant chunk
        const int rowbase = tid >> 4;        // 0..7
        const float4 w1a = *reinterpret_cast<const float4*>(w_u + ch * 8);
        const float4 w1b = *reinterpret_cast<const float4*>(w_u + ch * 8 + 4);
        const float4 w3a = *reinterpret_cast<const float4*>(w_u + 2 * H_ + ch * 8);
        const float4 w3b = *reinterpret_cast<const float4*>(w_u + 2 * H_ + ch * 8 + 4);
        #pragma unroll
        for (int l = 0; l < 8; l++) {
            const int row = rowbase + l * 8;          // 0..63
            const float* brow = body + base + (size_t)(i0 + row) * H_ + ch * 8;
            const float4 v0 = *reinterpret_cast<const float4*>(brow);
            const float4 v1 = *reinterpret_cast<const float4*>(brow + 4);
            uint4 chunk;
            chunk.x = pack_h2(v0.x * w3a.x, v0.y * w3a.y);
            chunk.y = pack_h2(v0.z * w3a.z, v0.w * w3a.w);
            chunk.z = pack_h2(v1.x * w3b.x, v1.y * w3b.y);
            chunk.w = pack_h2(v1.z * w3b.z, v1.w * w3b.w);
            *reinterpret_cast<uint4*>(smem + OFF_A
                + row * 256 + ((ch ^ (row & 7)) << 4)) = chunk;
            float sbp = v0.x*w1a.x + v0.y*w1a.y + v0.z*w1a.z + v0.w*w1a.w
                      + v1.x*w1b.x + v1.y*w1b.y + v1.z*w1b.z + v1.w*w1b.w;
            #pragma unroll
            for (int o = 8; o > 0; o >>= 1)
                sbp += __shfl_down_sync(0xFFFFFFFFu, sbp, o, 16);
            if (ch == 0) ((float*)(smem + OFF_SB))[row] = sbp;
        }
    }

    // gate ONLY the prep-produced data (g_Ph, g_spun)
    GRIDDEP_WAIT();

    // P(0) prefetch
    load_slab64(sbase + OFF_P0, g_Ph + base, 0, tid);
    CP_COMMIT();

    // full spun row (1024 f32)
    #pragma unroll
    for (int l = 0; l < 8; l++)
        ((float*)(smem + OFF_SP))[tid + l * 128] = g_spun[b * L_ + tid + l * 128];

    // fragment addressing (constant per thread)
    const int a_row  = (lane & 7) + ((lane >> 3) & 1) * 8;
    const int a_half = lane >> 4;
    const int b_row  = (lane & 7) + (lane >> 4) * 8;
    const int b_half = (lane >> 3) & 1;

    const float* sbV = (const float*)(smem + OFF_SB);
    const float* spV = (const float*)(smem + OFF_SP);
    const int r4 = lane >> 2;
    const int c2 = (lane & 3) << 1;

    CP_WAIT(0);        // P(0) arrived; A slab stores visible after barrier
    __syncthreads();

    // hoist ALL A fragments into registers (reused by all 16 j-tiles)
    uint32_t aF[2][8][4];
    #pragma unroll
    for (int mi = 0; mi < 2; mi++) {
        const int arow = m_base + mi * 16 + a_row;
        #pragma unroll
        for (int ks = 0; ks < 8; ks++) {
            const uint32_t off = (uint32_t)(arow * 256
                + (((ks * 2 + a_half) ^ (arow & 7)) << 4));
            ldsm_x4(aF[mi][ks], sbase + OFF_A + off);
        }
    }

    #pragma unroll 1
    for (int j = 0; j < 16; j++) {
        const uint32_t pbuf = sbase + ((j & 1) ? OFF_P1 : OFF_P0);
        const uint32_t obuf = sbase + ((j & 1) ? OFF_P0 : OFF_P1);

        if (j) { CP_WAIT(0); __syncthreads(); }   // P(j) ready

        float acc[2][4][4];
        #pragma unroll
        for (int mi = 0; mi < 2; mi++)
            #pragma unroll
            for (int ni = 0; ni < 4; ni++)
                #pragma unroll
                for (int k = 0; k < 4; k++) acc[mi][ni][k] = 0.f;

        #pragma unroll
        for (int ks = 0; ks < 8; ks++) {
            uint32_t bH[4][2];
            #pragma unroll
            for (int np = 0; np < 2; np++) {
                const int nrow = n_base + np * 16 + b_row;
                const uint32_t off = (uint32_t)(nrow * 256
                    + (((ks * 2 + b_half) ^ (nrow & 7)) << 4));
                uint32_t r[4];
                ldsm_x4(r, pbuf + off);
                bH[np*2][0] = r[0]; bH[np*2][1] = r[1];
                bH[np*2+1][0] = r[2]; bH[np*2+1][1] = r[3];
            }
            #pragma unroll
            for (int mi = 0; mi < 2; mi++)
                #pragma unroll
                for (int ni = 0; ni < 4; ni++)
                    mma_f16(acc[mi][ni], aF[mi][ks], bH[ni]);
        }
        __syncthreads();   // pbuf dead

        // all outstanding TMA groups are >= one compute phase old -> cheap
        if (tid == 0) BULK_WAIT0();
        __syncthreads();
        if (j < 15) {      // prefetch P(j+1) into obuf (overlaps epilogue)
            load_slab64(obuf, g_Ph + base, (j + 1) * 64, tid);
            CP_COMMIT();
        }

        // --- epilogue: both 32x64 regions staged concurrently into pbuf ---
        char* sub = smem + (pbuf - sbase) + wn * 8192;
        #pragma unroll
        for (int mi = 0; mi < 2; mi++) {
            const int row = m_base + mi * 16 + r4;       // CTA-local 0..63
            const float sb0 = sbV[row];
            const float sb1 = sbV[row + 8];
            #pragma unroll
            for (int ni = 0; ni < 4; ni++) {
                const int colR = ni * 8 + c2;            // region col 0..31
                const float sp0 = spV[j * 64 + n_base + colR];
                const float sp1 = spV[j * 64 + n_base + colR + 1];
                float2 v0 = make_float2(acc[mi][ni][0] + sb0 + sp0,
                                        acc[mi][ni][1] + sb0 + sp1);
                float2 v1 = make_float2(acc[mi][ni][2] + sb1 + sp0,
                                        acc[mi][ni][3] + sb1 + sp1);
                *reinterpret_cast<float2*>(sub + sw128((uint32_t)(row * 128 + colR * 4)))       = v0;
                *reinterpret_cast<float2*>(sub + sw128((uint32_t)((row + 8) * 128 + colR * 4))) = v1;
            }
        }
        __syncthreads();   // both regions staged
        if (tid == 0) {
            asm volatile("fence.proxy.async.shared::cta;" ::: "memory");
            const int y = b * L_ + i0;
            #pragma unroll
            for (int s = 0; s < 2; s++) {
                const int x = j * 64 + s * 32;
                const uint32_t sa = pbuf + s * 8192;
                asm volatile(
                    "cp.async.bulk.tensor.2d.global.shared::cta.tile.bulk_group "
                    "[%0, {%1, %2}], [%3];"
                    :: "l"(&tmap), "r"(x), "r"(y), "r"(sa) : "memory");
            }
            asm volatile("cp.async.bulk.commit_group;" ::: "memory");
        }
    }
    if (tid == 0) BULK_WAIT0();   // exit safety
}

// ---------------------------------------------------------------------------
// Launch
// ---------------------------------------------------------------------------
typedef CUresult (*EncFn)(CUtensorMap*, CUtensorMapDataType, cuuint32_t, void*,
                          const cuuint64_t*, const cuuint64_t*, const cuuint32_t*,
                          const cuuint32_t*, CUtensorMapInterleave, CUtensorMapSwizzle,
                          CUtensorMapL2promotion, CUtensorMapFloatOOBfill);

extern "C" void kernel_launch(void* const* d_in, const int* in_sizes, int n_in,
                              void* d_out, int out_size) {
    const float* body = (const float*)d_in[n_in - 3];
    const float* pun  = (const float*)d_in[n_in - 2];
    const float* w_u  = (const float*)d_in[n_in - 1];
    float* out = (float*)d_out;

    static CUtensorMap h_tmap;
    static bool init_done = false;
    if (!init_done) {
        void* fp = nullptr;
        cudaDriverEntryPointQueryResult qr;
        cudaGetDriverEntryPointByVersion("cuTensorMapEncodeTiled", &fp, 12000,
                                         cudaEnableDefault, &qr);
        // out viewed as 2D [B_*L_, L_] f32; box 32x64, SW128 (32*4B = 128B limit)
        cuuint64_t dims[2]    = {L_, (cuuint64_t)B_ * L_};
        cuuint64_t strides[1] = {L_ * sizeof(float)};
        cuuint32_t box[2]     = {32, 64};
        cuuint32_t es[2]      = {1, 1};
        ((EncFn)fp)(&h_tmap, CU_TENSOR_MAP_DATA_TYPE_FLOAT32, 2, d_out,
                    dims, strides, box, es,
                    CU_TENSOR_MAP_INTERLEAVE_NONE, CU_TENSOR_MAP_SWIZZLE_128B,
                    CU_TENSOR_MAP_L2_PROMOTION_L2_128B,
                    CU_TENSOR_MAP_FLOAT_OOB_FILL_NONE);
        cudaFuncSetAttribute(gemm_kernel, cudaFuncAttributeMaxDynamicSharedMemorySize,
                             SMEM_TOTAL);
        init_done = true;
    }

    prep_kernel<<<(B_ * L_) / 8, 256>>>(pun, w_u);

    // PDL launch: gemm starts while prep drains; griddepcontrol.wait inside
    // gates only the g_Ph / g_spun consumption.
    cudaLaunchConfig_t cfg = {};
    cfg.gridDim  = dim3(16, B_);
    cfg.blockDim = dim3(128);
    cfg.dynamicSmemBytes = SMEM_TOTAL;
    cudaLaunchAttribute attrs[1];
    attrs[0].id = cudaLaunchAttributeProgrammaticStreamSerialization;
    attrs[0].val.programmaticStreamSerializationAllowed = 1;
    cfg.attrs = attrs;
    cfg.numAttrs = 1;
    cudaLaunchKernelEx(&cfg, gemm_kernel, out, body, w_u, h_tmap);
}

// round 17
// speedup vs baseline: 1.0180x; 1.0180x over previous
#include <cuda_runtime.h>
#include <cuda_fp16.h>
#include <cuda.h>
#include <cstdint>

// Problem constants
#define B_  64
#define L_  1024
#define H_  128

// ---------------------------------------------------------------------------
// Scratch (allocation-free rule: __device__ globals)
// fp16 1-term scheme: ah = fp16(body*w3); ph = fp16(pun); s_cross ≈ ah·ph
// (measured rel_err 1.75e-4, deterministic inputs)
// A-side (ah, sbody) computed INSIDE the gemm kernel (tile-local, coalesced);
// prep only produces Ph + spun. PDL kept (harmless).
// ---------------------------------------------------------------------------
__device__ __align__(16) __half g_Ph[(size_t)B_*L_*H_];
__device__ float g_spun [B_*L_];

// ---------------------------------------------------------------------------
// Helpers (base-arch only: NO tcgen05 — ptxas target is sm_103, not sm_103a.
// cp.async.bulk.tensor and griddepcontrol ARE base sm_90+.)
// ---------------------------------------------------------------------------
__device__ __forceinline__ uint32_t smem_u32(const void* p) {
    uint32_t a;
    asm("{ .reg .u64 t; cvta.to.shared.u64 t, %1; cvt.u32.u64 %0, t; }" : "=r"(a) : "l"(p));
    return a;
}

__device__ __forceinline__ void ldsm_x4(uint32_t* r, uint32_t addr) {
    asm volatile("ldmatrix.sync.aligned.m8n8.x4.shared.b16 {%0,%1,%2,%3}, [%4];"
        : "=r"(r[0]), "=r"(r[1]), "=r"(r[2]), "=r"(r[3]) : "r"(addr));
}

// D += A * B  (m16n8k16, fp16 in, f32 accum)
__device__ __forceinline__ void mma_f16(float* d, const uint32_t* a, const uint32_t* b) {
    asm volatile(
        "mma.sync.aligned.m16n8k16.row.col.f32.f16.f16.f32 "
        "{%0,%1,%2,%3}, {%4,%5,%6,%7}, {%8,%9}, {%0,%1,%2,%3};"
        : "+f"(d[0]), "+f"(d[1]), "+f"(d[2]), "+f"(d[3])
        : "r"(a[0]), "r"(a[1]), "r"(a[2]), "r"(a[3]), "r"(b[0]), "r"(b[1]));
}

__device__ __forceinline__ void cp_async16(uint32_t dst, const void* src) {
    asm volatile("cp.async.cg.shared.global [%0], [%1], 16;" :: "r"(dst), "l"(src));
}
#define CP_COMMIT() asm volatile("cp.async.commit_group;" ::: "memory")
#define CP_WAIT(n)  asm volatile("cp.async.wait_group %0;" :: "n"(n) : "memory")
#define BULK_WAIT0() asm volatile("cp.async.bulk.wait_group 0;" ::: "memory")
#define GRIDDEP_WAIT()   asm volatile("griddepcontrol.wait;" ::: "memory")
#define GRIDDEP_LAUNCH() asm volatile("griddepcontrol.launch_dependents;" ::: "memory")

// SW128 swizzle for 128B-pitch rows (epilogue staging / TMA)
__device__ __forceinline__ uint32_t sw128(uint32_t byte_off) {
    return byte_off ^ ((byte_off >> 3) & 0x70u);
}

__device__ __forceinline__ uint32_t pack_h2(float x, float y) {
    __half2 v(__float2half(x), __float2half(y));
    return *reinterpret_cast<uint32_t*>(&v);
}

// ---------------------------------------------------------------------------
// Kernel 1: preprocess (P-side only) — ph = fp16(pun); spun = dot(pun, w2).
// 2 rows per warp (independent LDG chains -> MLP 2).
// ---------------------------------------------------------------------------
__global__ void __launch_bounds__(256) prep_kernel(const float* __restrict__ pun,
                                                   const float* __restrict__ w_u) {
    const int warp = threadIdx.x >> 5, lane = threadIdx.x & 31;
    const int r0 = blockIdx.x * 16 + warp * 2;    // rows r0, r0+1
    const int d4 = lane * 4;

    const float4 w2 = *reinterpret_cast<const float4*>(w_u + H_ + d4);

    const size_t idx0 = (size_t)r0 * H_ + d4;
    const size_t idx1 = idx0 + H_;
    const float4 p0 = *reinterpret_cast<const float4*>(pun + idx0);
    const float4 p1 = *reinterpret_cast<const float4*>(pun + idx1);

    *reinterpret_cast<uint2*>(g_Ph + idx0) =
        make_uint2(pack_h2(p0.x, p0.y), pack_h2(p0.z, p0.w));
    *reinterpret_cast<uint2*>(g_Ph + idx1) =
        make_uint2(pack_h2(p1.x, p1.y), pack_h2(p1.z, p1.w));

    float s0 = p0.x * w2.x + p0.y * w2.y + p0.z * w2.z + p0.w * w2.w;
    float s1 = p1.x * w2.x + p1.y * w2.y + p1.z * w2.z + p1.w * w2.w;
    #pragma unroll
    for (int o = 16; o > 0; o >>= 1) {
        s0 += __shfl_down_sync(0xFFFFFFFFu, s0, o);
        s1 += __shfl_down_sync(0xFFFFFFFFu, s1, o);
    }
    if (lane == 0) { g_spun[r0] = s0; g_spun[r0 + 1] = s1; }

    GRIDDEP_LAUNCH();
}

// ---------------------------------------------------------------------------
// Kernel 2: occupancy-4 fused-j batched GEMM with coalesced fused A-convert.
//   CTA = (64-row i-block, batch), 128 threads, 2x2 warps, warp tile 32x32.
//   A FRAGMENTS HOISTED IN REGISTERS for all 16 j-tiles.
//   P double-buffered (16 KB); epilogue stages both 32x64 regions into the
//   dead P buffer, one TMA group per j. 3 barriers per j (TMA drain folded
//   into the compute phase: tid0 BULK_WAITs while other warps finish MMAs).
// Slab format (A and P): rows x 256B (128 fp16); 16B chunk swizzle
//   phys = row*256 + ((ch ^ (row&7))<<4)
// ---------------------------------------------------------------------------
static constexpr int OFF_SB = 0;        // 64 f32 sbody slice (computed in-CTA)
static constexpr int OFF_SP = 512;      // 1024 f32 spun (full row)
static constexpr int OFF_A  = 5120;     // 16 KB A slab (64 rows)
static constexpr int OFF_P0 = 21504;    // 16 KB P slab 0 (64 j-cols)
static constexpr int OFF_P1 = 37888;    // 16 KB P slab 1
static constexpr int SMEM_TOTAL = 54272;    // -> occupancy 4 (regs <= 128)

__device__ __forceinline__ void load_slab64(uint32_t dst, const __half* __restrict__ g,
                                            int row0, int tid) {
    #pragma unroll
    for (int l = 0; l < 8; l++) {
        const int cidx = tid + l * 128;     // 0..1023 16B chunks
        const int row  = cidx >> 4;         // 0..63
        const int ch   = cidx & 15;
        const uint32_t off = (uint32_t)(row * 256 + ((ch ^ (row & 7)) << 4));
        cp_async16(dst + off, g + (size_t)(row0 + row) * H_ + ch * 8);
    }
}

__global__ void __launch_bounds__(128, 4)
gemm_kernel(float* __restrict__ out, const float* __restrict__ body,
            const float* __restrict__ w_u, const __grid_constant__ CUtensorMap tmap) {
    extern __shared__ char smem[];
    const uint32_t sbase = smem_u32(smem);
    const int tid  = threadIdx.x;
    const int lane = tid & 31;
    const int warp = tid >> 5;
    const int wm = warp & 1;            // 2 warps over M (32 rows each)
    const int wn = warp >> 1;           // 2 warps over N (32 cols each)
    const int m_base = wm * 32, n_base = wn * 32;

    const int i0 = blockIdx.x * 64;     // 16 i-blocks of 64 rows
    const int b  = blockIdx.y;
    const size_t base = (size_t)b * L_ * H_;

    // --- fused A-conversion + sbody (coalesced) — independent of prep ---
    {
        const int ch      = tid & 15;        // loop-invariant chunk
        const int rowbase = tid >> 4;        // 0..7
        const float4 w1a = *reinterpret_cast<const float4*>(w_u + ch * 8);
        const float4 w1b = *reinterpret_cast<const float4*>(w_u + ch * 8 + 4);
        const float4 w3a = *reinterpret_cast<const float4*>(w_u + 2 * H_ + ch * 8);
        const float4 w3b = *reinterpret_cast<const float4*>(w_u + 2 * H_ + ch * 8 + 4);
        #pragma unroll
        for (int l = 0; l < 8; l++) {
            const int row = rowbase + l * 8;          // 0..63
            const float* brow = body + base + (size_t)(i0 + row) * H_ + ch * 8;
            const float4 v0 = *reinterpret_cast<const float4*>(brow);
            const float4 v1 = *reinterpret_cast<const float4*>(brow + 4);
            uint4 chunk;
            chunk.x = pack_h2(v0.x * w3a.x, v0.y * w3a.y);
            chunk.y = pack_h2(v0.z * w3a.z, v0.w * w3a.w);
            chunk.z = pack_h2(v1.x * w3b.x, v1.y * w3b.y);
            chunk.w = pack_h2(v1.z * w3b.z, v1.w * w3b.w);
            *reinterpret_cast<uint4*>(smem + OFF_A
                + row * 256 + ((ch ^ (row & 7)) << 4)) = chunk;
            float sbp = v0.x*w1a.x + v0.y*w1a.y + v0.z*w1a.z + v0.w*w1a.w
                      + v1.x*w1b.x + v1.y*w1b.y + v1.z*w1b.z + v1.w*w1b.w;
            #pragma unroll
            for (int o = 8; o > 0; o >>= 1)
                sbp += __shfl_down_sync(0xFFFFFFFFu, sbp, o, 16);
            if (ch == 0) ((float*)(smem + OFF_SB))[row] = sbp;
        }
    }

    // gate ONLY the prep-produced data (g_Ph, g_spun)
    GRIDDEP_WAIT();

    // P(0) prefetch
    load_slab64(sbase + OFF_P0, g_Ph + base, 0, tid);
    CP_COMMIT();

    // full spun row (1024 f32)
    #pragma unroll
    for (int l = 0; l < 8; l++)
        ((float*)(smem + OFF_SP))[tid + l * 128] = g_spun[b * L_ + tid + l * 128];

    // fragment addressing (constant per thread)
    const int a_row  = (lane & 7) + ((lane >> 3) & 1) * 8;
    const int a_half = lane >> 4;
    const int b_row  = (lane & 7) + (lane >> 4) * 8;
    const int b_half = (lane >> 3) & 1;

    const float* sbV = (const float*)(smem + OFF_SB);
    const float* spV = (const float*)(smem + OFF_SP);
    const int r4 = lane >> 2;
    const int c2 = (lane & 3) << 1;

    CP_WAIT(0);        // P(0) arrived; A slab stores visible after barrier
    __syncthreads();

    // hoist ALL A fragments into registers (reused by all 16 j-tiles)
    uint32_t aF[2][8][4];
    #pragma unroll
    for (int mi = 0; mi < 2; mi++) {
        const int arow = m_base + mi * 16 + a_row;
        #pragma unroll
        for (int ks = 0; ks < 8; ks++) {
            const uint32_t off = (uint32_t)(arow * 256
                + (((ks * 2 + a_half) ^ (arow & 7)) << 4));
            ldsm_x4(aF[mi][ks], sbase + OFF_A + off);
        }
    }

    #pragma unroll 1
    for (int j = 0; j < 16; j++) {
        const uint32_t pbuf = sbase + ((j & 1) ? OFF_P1 : OFF_P0);
        const uint32_t obuf = sbase + ((j & 1) ? OFF_P0 : OFF_P1);

        if (j) { CP_WAIT(0); __syncthreads(); }   // P(j) ready

        float acc[2][4][4];
        #pragma unroll
        for (int mi = 0; mi < 2; mi++)
            #pragma unroll
            for (int ni = 0; ni < 4; ni++)
                #pragma unroll
                for (int k = 0; k < 4; k++) acc[mi][ni][k] = 0.f;

        #pragma unroll
        for (int ks = 0; ks < 8; ks++) {
            uint32_t bH[4][2];
            #pragma unroll
            for (int np = 0; np < 2; np++) {
                const int nrow = n_base + np * 16 + b_row;
                const uint32_t off = (uint32_t)(nrow * 256
                    + (((ks * 2 + b_half) ^ (nrow & 7)) << 4));
                uint32_t r[4];
                ldsm_x4(r, pbuf + off);
                bH[np*2][0] = r[0]; bH[np*2][1] = r[1];
                bH[np*2+1][0] = r[2]; bH[np*2+1][1] = r[3];
            }
            #pragma unroll
            for (int mi = 0; mi < 2; mi++)
                #pragma unroll
                for (int ni = 0; ni < 4; ni++)
                    mma_f16(acc[mi][ni], aF[mi][ks], bH[ni]);
        }
        // TMA drain folded into compute phase: groups were committed at j-1,
        // independent of the other warps' MMAs still in flight.
        if (tid == 0) BULK_WAIT0();
        __syncthreads();   // compute done on pbuf + old TMA drained

        if (j < 15) {      // prefetch P(j+1) into obuf (overlaps epilogue)
            load_slab64(obuf, g_Ph + base, (j + 1) * 64, tid);
            CP_COMMIT();
        }

        // --- epilogue: both 32x64 regions staged concurrently into pbuf ---
        char* sub = smem + (pbuf - sbase) + wn * 8192;
        #pragma unroll
        for (int mi = 0; mi < 2; mi++) {
            const int row = m_base + mi * 16 + r4;       // CTA-local 0..63
            const float sb0 = sbV[row];
            const float sb1 = sbV[row + 8];
            #pragma unroll
            for (int ni = 0; ni < 4; ni++) {
                const int colR = ni * 8 + c2;            // region col 0..31
                const float sp0 = spV[j * 64 + n_base + colR];
                const float sp1 = spV[j * 64 + n_base + colR + 1];
                float2 v0 = make_float2(acc[mi][ni][0] + sb0 + sp0,
                                        acc[mi][ni][1] + sb0 + sp1);
                float2 v1 = make_float2(acc[mi][ni][2] + sb1 + sp0,
                                        acc[mi][ni][3] + sb1 + sp1);
                *reinterpret_cast<float2*>(sub + sw128((uint32_t)(row * 128 + colR * 4)))       = v0;
                *reinterpret_cast<float2*>(sub + sw128((uint32_t)((row + 8) * 128 + colR * 4))) = v1;
            }
        }
        __syncthreads();   // both regions staged
        if (tid == 0) {
            asm volatile("fence.proxy.async.shared::cta;" ::: "memory");
            const int y = b * L_ + i0;
            #pragma unroll
            for (int s = 0; s < 2; s++) {
                const int x = j * 64 + s * 32;
                const uint32_t sa = pbuf + s * 8192;
                asm volatile(
                    "cp.async.bulk.tensor.2d.global.shared::cta.tile.bulk_group "
                    "[%0, {%1, %2}], [%3];"
                    :: "l"(&tmap), "r"(x), "r"(y), "r"(sa) : "memory");
            }
            asm volatile("cp.async.bulk.commit_group;" ::: "memory");
        }
    }
    if (tid == 0) BULK_WAIT0();   // exit safety
}

// ---------------------------------------------------------------------------
// Launch
// ---------------------------------------------------------------------------
typedef CUresult (*EncFn)(CUtensorMap*, CUtensorMapDataType, cuuint32_t, void*,
                          const cuuint64_t*, const cuuint64_t*, const cuuint32_t*,
                          const cuuint32_t*, CUtensorMapInterleave, CUtensorMapSwizzle,
                          CUtensorMapL2promotion, CUtensorMapFloatOOBfill);

extern "C" void kernel_launch(void* const* d_in, const int* in_sizes, int n_in,
                              void* d_out, int out_size) {
    const float* body = (const float*)d_in[n_in - 3];
    const float* pun  = (const float*)d_in[n_in - 2];
    const float* w_u  = (const float*)d_in[n_in - 1];
    float* out = (float*)d_out;

    static CUtensorMap h_tmap;
    static bool init_done = false;
    if (!init_done) {
        void* fp = nullptr;
        cudaDriverEntryPointQueryResult qr;
        cudaGetDriverEntryPointByVersion("cuTensorMapEncodeTiled", &fp, 12000,
                                         cudaEnableDefault, &qr);
        // out viewed as 2D [B_*L_, L_] f32; box 32x64, SW128 (32*4B = 128B limit)
        cuuint64_t dims[2]    = {L_, (cuuint64_t)B_ * L_};
        cuuint64_t strides[1] = {L_ * sizeof(float)};
        cuuint32_t box[2]     = {32, 64};
        cuuint32_t es[2]      = {1, 1};
        ((EncFn)fp)(&h_tmap, CU_TENSOR_MAP_DATA_TYPE_FLOAT32, 2, d_out,
                    dims, strides, box, es,
                    CU_TENSOR_MAP_INTERLEAVE_NONE, CU_TENSOR_MAP_SWIZZLE_128B,
                    CU_TENSOR_MAP_L2_PROMOTION_L2_128B,
                    CU_TENSOR_MAP_FLOAT_OOB_FILL_NONE);
        cudaFuncSetAttribute(gemm_kernel, cudaFuncAttributeMaxDynamicSharedMemorySize,
                             SMEM_TOTAL);
        init_done = true;
    }

    prep_kernel<<<(B_ * L_) / 16, 256>>>(pun, w_u);

    // PDL launch (kept from round 16; neutral but harmless)
    cudaLaunchConfig_t cfg = {};
    cfg.gridDim  = dim3(16, B_);
    cfg.blockDim = dim3(128);
    cfg.dynamicSmemBytes = SMEM_TOTAL;
    cudaLaunchAttribute attrs[1];
    attrs[0].id = cudaLaunchAttributeProgrammaticStreamSerialization;
    attrs[0].val.programmaticStreamSerializationAllowed = 1;
    cfg.attrs = attrs;
    cfg.numAttrs = 1;
    cudaLaunchKernelEx(&cfg, gemm_kernel, out, body, w_u, h_tmap);
}